// round 9
// baseline (speedup 1.0000x reference)
#include <cuda_runtime.h>
#include <cuda_fp16.h>
#include <math.h>
#include <stdint.h>

// Problem constants (fixed by setup_inputs)
#define N_NODES 32768
#define E_EDGES 524288
#define F_IN    128
#define D1      256
#define D2      128
#define NT      3
#define SEQ     16
#define NNG     512

// ---------------- scratch (device globals; no allocation allowed) ----------------
__device__ __half g_xh  [N_NODES * F_IN];            // 8 MB normalized x, fp16
__device__ __half g_agg [NT * N_NODES * F_IN];       // 24 MB aggregated xn, fp16
__device__ __half g_h1r [NT * N_NODES * D1];         // 48 MB relu(agg@W1+b1), fp16
__device__ __half g_h2  [NT * N_NODES * D2];         // 24 MB h1r@W2, fp16
__device__ float  g_deg [NT * N_NODES];
__device__ float  g_dis [NT * N_NODES];
__device__ int    g_counts[N_NODES];
__device__ int    g_rowptr[N_NODES + 1];
__device__ int    g_cursor[N_NODES];
__device__ float4 g_meta[E_EDGES];                   // {w0,w1,w2,src-as-float} CSR by dst
__device__ float  g_colsum[F_IN];
__device__ float  g_colsq [F_IN];
__device__ float  g_mean[F_IN];
__device__ float  g_rstd[F_IN];

// ---------------- helpers ----------------
__device__ __forceinline__ uint32_t f2tf32(float f) {
    uint32_t r;
    asm("cvt.rna.tf32.f32 %0, %1;" : "=r"(r) : "f"(f));
    return r;
}
__device__ __forceinline__ void mma_tf32(float* c,
    uint32_t a0, uint32_t a1, uint32_t a2, uint32_t a3,
    uint32_t b0, uint32_t b1)
{
    asm volatile(
        "mma.sync.aligned.m16n8k8.row.col.f32.tf32.tf32.f32 "
        "{%0,%1,%2,%3}, {%4,%5,%6,%7}, {%8,%9}, {%0,%1,%2,%3};"
        : "+f"(c[0]), "+f"(c[1]), "+f"(c[2]), "+f"(c[3])
        : "r"(a0), "r"(a1), "r"(a2), "r"(a3), "r"(b0), "r"(b1));
}
__device__ __forceinline__ uint32_t pack_h2(float a, float b) {
    __half2 h = __floats2half2_rn(a, b);
    return *(uint32_t*)&h;
}
__device__ __forceinline__ float2 uph2(uint32_t u) {
    return __half22float2(*(__half2*)&u);
}

// ---------------- small prep kernels ----------------
__global__ void zero_kernel() {
    int i = blockIdx.x * 256 + threadIdx.x;
    if (i < N_NODES)      g_counts[i] = 0;
    if (i < NT * N_NODES) g_deg[i] = 0.0f;
    if (i < F_IN) { g_colsum[i] = 0.0f; g_colsq[i] = 0.0f; }
}

__global__ void stats_kernel(const float* __restrict__ x) {
    int c  = threadIdx.x;
    int r0 = blockIdx.x * 256;
    float s = 0.0f, q = 0.0f;
    for (int r = 0; r < 256; r++) {
        float v = x[(r0 + r) * F_IN + c];
        s += v; q += v * v;
    }
    atomicAdd(&g_colsum[c], s);
    atomicAdd(&g_colsq[c],  q);
}

__global__ void finstats_kernel() {
    int c = threadIdx.x;
    float n = (float)N_NODES;
    float mean = g_colsum[c] / n;
    float var  = (g_colsq[c] - n * mean * mean) / (n - 1.0f);  // ddof=1
    g_mean[c] = mean;
    g_rstd[c] = rsqrtf(var);
}

// normalize x -> fp16 table
__global__ void xnorm_kernel(const float* __restrict__ x) {
    int i  = blockIdx.x * 256 + threadIdx.x;  // float4 index
    int c4 = (i & 31) * 4;
    float4 v = ((const float4*)x)[i];
    v.x = (v.x - g_mean[c4 + 0]) * g_rstd[c4 + 0];
    v.y = (v.y - g_mean[c4 + 1]) * g_rstd[c4 + 1];
    v.z = (v.z - g_mean[c4 + 2]) * g_rstd[c4 + 2];
    v.w = (v.w - g_mean[c4 + 3]) * g_rstd[c4 + 3];
    uint2 o = make_uint2(pack_h2(v.x, v.y), pack_h2(v.z, v.w));
    ((uint2*)g_xh)[i] = o;
}

__global__ void hist_kernel(const int* __restrict__ ei, const float* __restrict__ ea) {
    int e = blockIdx.x * 256 + threadIdx.x;
    if (e >= E_EDGES) return;
    int dst = ei[E_EDGES + e];
    atomicAdd(&g_counts[dst], 1);
    atomicAdd(&g_deg[0 * N_NODES + dst], fabsf(ea[3 * e + 0]));
    atomicAdd(&g_deg[1 * N_NODES + dst], fabsf(ea[3 * e + 1]));
    atomicAdd(&g_deg[2 * N_NODES + dst], fabsf(ea[3 * e + 2]));
}

__global__ void scan_kernel() {
    __shared__ int sums[1024];
    int tid  = threadIdx.x;
    int base = tid * 32;
    int vals[32];
    int s = 0;
#pragma unroll
    for (int i = 0; i < 32; i++) { int v = g_counts[base + i]; vals[i] = s; s += v; }
    sums[tid] = s;
    __syncthreads();
    for (int off = 1; off < 1024; off <<= 1) {
        int v = (tid >= off) ? sums[tid - off] : 0;
        __syncthreads();
        sums[tid] += v;
        __syncthreads();
    }
    int ex = (tid > 0) ? sums[tid - 1] : 0;
#pragma unroll
    for (int i = 0; i < 32; i++) {
        int p = ex + vals[i];
        g_rowptr[base + i] = p;
        g_cursor[base + i] = p;
    }
    if (tid == 1023) g_rowptr[N_NODES] = sums[1023];
}

__global__ void dis_kernel() {
    int i = blockIdx.x * 256 + threadIdx.x;
    if (i < NT * N_NODES) g_dis[i] = rsqrtf(g_deg[i] + 1.0f);
}

__global__ void fill_kernel(const int* __restrict__ ei, const float* __restrict__ ea) {
    int e = blockIdx.x * 256 + threadIdx.x;
    if (e >= E_EDGES) return;
    int src = ei[e];
    int dst = ei[E_EDGES + e];
    int pos = atomicAdd(&g_cursor[dst], 1);
    float4 m;
    m.x = g_dis[0 * N_NODES + src] * fabsf(ea[3 * e + 0]) * g_dis[0 * N_NODES + dst];
    m.y = g_dis[1 * N_NODES + src] * fabsf(ea[3 * e + 1]) * g_dis[1 * N_NODES + dst];
    m.z = g_dis[2 * N_NODES + src] * fabsf(ea[3 * e + 2]) * g_dis[2 * N_NODES + dst];
    m.w = __int_as_float(src);
    g_meta[pos] = m;
}

// ---------------- fused 3-type aggregation of fp16 xn ----------------
// 2 warps per node: warp-half h handles features [h*64, h*64+64) (one uint32 per lane).
// 4-edge unroll: 4 meta + 4 row loads in flight.
__global__ void gather0_kernel() {
    int lane = threadIdx.x & 31;
    int wu   = threadIdx.x >> 5;                  // 0..7
    int v    = blockIdx.x * 4 + (wu >> 1);        // 8192 blocks * 4 nodes
    int off  = (wu & 1) * 32 + lane;              // uint index within 64-uint row

    const uint32_t* __restrict__ xh = (const uint32_t*)g_xh;
    int beg = g_rowptr[v];
    int end = g_rowptr[v + 1];

    float2 a0 = make_float2(0.f, 0.f);
    float2 a1 = make_float2(0.f, 0.f);
    float2 a2 = make_float2(0.f, 0.f);

    int j = beg;
    for (; j + 3 < end; j += 4) {
        float4 m0 = __ldg(&g_meta[j]);
        float4 m1 = __ldg(&g_meta[j + 1]);
        float4 m2 = __ldg(&g_meta[j + 2]);
        float4 m3 = __ldg(&g_meta[j + 3]);
        uint32_t r0 = xh[__float_as_int(m0.w) * 64 + off];
        uint32_t r1 = xh[__float_as_int(m1.w) * 64 + off];
        uint32_t r2 = xh[__float_as_int(m2.w) * 64 + off];
        uint32_t r3 = xh[__float_as_int(m3.w) * 64 + off];
        float2 f0 = uph2(r0), f1 = uph2(r1), f2 = uph2(r2), f3 = uph2(r3);
        a0.x = fmaf(m0.x, f0.x, a0.x); a0.y = fmaf(m0.x, f0.y, a0.y);
        a1.x = fmaf(m0.y, f0.x, a1.x); a1.y = fmaf(m0.y, f0.y, a1.y);
        a2.x = fmaf(m0.z, f0.x, a2.x); a2.y = fmaf(m0.z, f0.y, a2.y);
        a0.x = fmaf(m1.x, f1.x, a0.x); a0.y = fmaf(m1.x, f1.y, a0.y);
        a1.x = fmaf(m1.y, f1.x, a1.x); a1.y = fmaf(m1.y, f1.y, a1.y);
        a2.x = fmaf(m1.z, f1.x, a2.x); a2.y = fmaf(m1.z, f1.y, a2.y);
        a0.x = fmaf(m2.x, f2.x, a0.x); a0.y = fmaf(m2.x, f2.y, a0.y);
        a1.x = fmaf(m2.y, f2.x, a1.x); a1.y = fmaf(m2.y, f2.y, a1.y);
        a2.x = fmaf(m2.z, f2.x, a2.x); a2.y = fmaf(m2.z, f2.y, a2.y);
        a0.x = fmaf(m3.x, f3.x, a0.x); a0.y = fmaf(m3.x, f3.y, a0.y);
        a1.x = fmaf(m3.y, f3.x, a1.x); a1.y = fmaf(m3.y, f3.y, a1.y);
        a2.x = fmaf(m3.z, f3.x, a2.x); a2.y = fmaf(m3.z, f3.y, a2.y);
    }
    for (; j < end; j++) {
        float4 m = __ldg(&g_meta[j]);
        float2 f = uph2(xh[__float_as_int(m.w) * 64 + off]);
        a0.x = fmaf(m.x, f.x, a0.x); a0.y = fmaf(m.x, f.y, a0.y);
        a1.x = fmaf(m.y, f.x, a1.x); a1.y = fmaf(m.y, f.y, a1.y);
        a2.x = fmaf(m.z, f.x, a2.x); a2.y = fmaf(m.z, f.y, a2.y);
    }

    float2 fv = uph2(xh[v * 64 + off]);
    float i0 = g_dis[0 * N_NODES + v]; i0 *= i0;
    float i1 = g_dis[1 * N_NODES + v]; i1 *= i1;
    float i2 = g_dis[2 * N_NODES + v]; i2 *= i2;
    a0.x = fmaf(i0, fv.x, a0.x); a0.y = fmaf(i0, fv.y, a0.y);
    a1.x = fmaf(i1, fv.x, a1.x); a1.y = fmaf(i1, fv.y, a1.y);
    a2.x = fmaf(i2, fv.x, a2.x); a2.y = fmaf(i2, fv.y, a2.y);

    uint32_t* o = (uint32_t*)g_agg;
    o[(0 * N_NODES + v) * 64 + off] = pack_h2(a0.x, a0.y);
    o[(1 * N_NODES + v) * 64 + off] = pack_h2(a1.x, a1.y);
    o[(2 * N_NODES + v) * 64 + off] = pack_h2(a2.x, a2.y);
}

// ---------------- tf32 mma.sync GEMM: C[M,N](fp16) = A(fp16)[M,K] @ W(fp32)[K,N] ----------------
__global__ void __launch_bounds__(256) gemm_mma(
    const __half* __restrict__ Abase, long long Astride,
    const float* __restrict__ Wbase, long long Wstride,
    __half* __restrict__ Cbase, long long Cstride,
    const float* __restrict__ biasBase, int biasStride,
    int M, int N, int K, int doRelu)
{
    __shared__ uint32_t As[128][36];   // [m][k] tf32
    __shared__ uint32_t Bs[32][136];   // [k][n] tf32

    const int t = blockIdx.z;
    const __half* A = Abase + (long long)t * Astride;
    const float*  W = Wbase + (long long)t * Wstride;
    __half*       C = Cbase + (long long)t * Cstride;

    const int tid  = threadIdx.x;
    const int wid  = tid >> 5;
    const int lane = tid & 31;
    const int gid  = lane >> 2;
    const int tig  = lane & 3;
    const int wm0  = (wid & 1) * 64;
    const int wn0  = (wid >> 1) * 32;
    const int bm0  = blockIdx.y * 128;
    const int bn0  = blockIdx.x * 128;

    float acc[4][4][4];
#pragma unroll
    for (int i = 0; i < 4; i++)
#pragma unroll
        for (int j = 0; j < 4; j++)
#pragma unroll
            for (int q = 0; q < 4; q++) acc[i][j][q] = 0.0f;

    const int nch = K >> 5;
    for (int c = 0; c < nch; c++) {
        // A tile: 128 x 32 halves -> tf32
#pragma unroll
        for (int it = 0; it < 2; it++) {
            int idx = tid + it * 256;              // 0..511, 8 halves each
            int r = idx >> 2, c8 = idx & 3;
            const __half* ap = A + (long long)(bm0 + r) * K + (c << 5) + c8 * 8;
            uint4 v = *(const uint4*)ap;
            const uint32_t* pw = &v.x;
#pragma unroll
            for (int q = 0; q < 4; q++) {
                float2 f = __half22float2(*(const __half2*)&pw[q]);
                As[r][c8 * 8 + q * 2]     = f2tf32(f.x);
                As[r][c8 * 8 + q * 2 + 1] = f2tf32(f.y);
            }
        }
        // B tile: 32 x 128 floats -> tf32
#pragma unroll
        for (int it = 0; it < 4; it++) {
            int idx = tid + it * 256;
            int k = idx >> 5, n4 = idx & 31;
            float4 v = *(const float4*)(W + (long long)((c << 5) + k) * N + bn0 + n4 * 4);
            uint4 o = make_uint4(f2tf32(v.x), f2tf32(v.y), f2tf32(v.z), f2tf32(v.w));
            *(uint4*)&Bs[k][n4 * 4] = o;
        }
        __syncthreads();

#pragma unroll
        for (int ks = 0; ks < 4; ks++) {
            int kk = ks * 8;
            uint32_t bf[4][2];
#pragma unroll
            for (int nf = 0; nf < 4; nf++) {
                bf[nf][0] = Bs[kk + tig][wn0 + nf * 8 + gid];
                bf[nf][1] = Bs[kk + tig + 4][wn0 + nf * 8 + gid];
            }
#pragma unroll
            for (int mf = 0; mf < 4; mf++) {
                int r = wm0 + mf * 16 + gid;
                uint32_t a0 = As[r][kk + tig];
                uint32_t a1 = As[r + 8][kk + tig];
                uint32_t a2 = As[r][kk + tig + 4];
                uint32_t a3 = As[r + 8][kk + tig + 4];
#pragma unroll
                for (int nf = 0; nf < 4; nf++)
                    mma_tf32(acc[mf][nf], a0, a1, a2, a3, bf[nf][0], bf[nf][1]);
            }
        }
        __syncthreads();
    }

    // epilogue: bias + relu, __half2 stores
#pragma unroll
    for (int mf = 0; mf < 4; mf++) {
        int row = bm0 + wm0 + mf * 16 + gid;
#pragma unroll
        for (int nf = 0; nf < 4; nf++) {
            int col = bn0 + wn0 + nf * 8 + tig * 2;
            float b0 = 0.0f, b1 = 0.0f;
            if (biasBase) {
                const float* bp = biasBase + (long long)t * biasStride + col;
                b0 = bp[0]; b1 = bp[1];
            }
            float o0 = acc[mf][nf][0] + b0;
            float o1 = acc[mf][nf][1] + b1;
            float o2 = acc[mf][nf][2] + b0;
            float o3 = acc[mf][nf][3] + b1;
            if (doRelu) {
                o0 = fmaxf(o0, 0.f); o1 = fmaxf(o1, 0.f);
                o2 = fmaxf(o2, 0.f); o3 = fmaxf(o3, 0.f);
            }
            *(__half2*)(C + (long long)row * N + col)       = __floats2half2_rn(o0, o1);
            *(__half2*)(C + (long long)(row + 8) * N + col) = __floats2half2_rn(o2, o3);
        }
    }
}

// ---------------- layer-2 gather: 2 warps/node, 3 types fused, + output permutation ----------
__global__ void gather2_kernel(const float* __restrict__ b2, float* __restrict__ out) {
    int lane = threadIdx.x & 31;
    int wu   = threadIdx.x >> 5;
    int v    = blockIdx.x * 4 + (wu >> 1);
    int off  = (wu & 1) * 32 + lane;              // uint index within 64-uint row

    const uint32_t* __restrict__ h2a = (const uint32_t*)(g_h2);
    const uint32_t* __restrict__ h2b = (const uint32_t*)(g_h2 + (long long)N_NODES * D2);
    const uint32_t* __restrict__ h2c = (const uint32_t*)(g_h2 + 2LL * N_NODES * D2);
    int beg = g_rowptr[v];
    int end = g_rowptr[v + 1];

    float2 a0 = make_float2(0.f, 0.f);
    float2 a1 = make_float2(0.f, 0.f);
    float2 a2 = make_float2(0.f, 0.f);

    int j = beg;
    for (; j + 1 < end; j += 2) {
        float4 mA = __ldg(&g_meta[j]);
        float4 mB = __ldg(&g_meta[j + 1]);
        int sA = __float_as_int(mA.w) * 64 + off;
        int sB = __float_as_int(mB.w) * 64 + off;
        uint32_t rA0 = h2a[sA], rA1 = h2b[sA], rA2 = h2c[sA];
        uint32_t rB0 = h2a[sB], rB1 = h2b[sB], rB2 = h2c[sB];
        float2 fA0 = uph2(rA0), fA1 = uph2(rA1), fA2 = uph2(rA2);
        float2 fB0 = uph2(rB0), fB1 = uph2(rB1), fB2 = uph2(rB2);
        a0.x = fmaf(mA.x, fA0.x, a0.x); a0.y = fmaf(mA.x, fA0.y, a0.y);
        a1.x = fmaf(mA.y, fA1.x, a1.x); a1.y = fmaf(mA.y, fA1.y, a1.y);
        a2.x = fmaf(mA.z, fA2.x, a2.x); a2.y = fmaf(mA.z, fA2.y, a2.y);
        a0.x = fmaf(mB.x, fB0.x, a0.x); a0.y = fmaf(mB.x, fB0.y, a0.y);
        a1.x = fmaf(mB.y, fB1.x, a1.x); a1.y = fmaf(mB.y, fB1.y, a1.y);
        a2.x = fmaf(mB.z, fB2.x, a2.x); a2.y = fmaf(mB.z, fB2.y, a2.y);
    }
    if (j < end) {
        float4 m = __ldg(&g_meta[j]);
        int s = __float_as_int(m.w) * 64 + off;
        float2 f0 = uph2(h2a[s]), f1 = uph2(h2b[s]), f2 = uph2(h2c[s]);
        a0.x = fmaf(m.x, f0.x, a0.x); a0.y = fmaf(m.x, f0.y, a0.y);
        a1.x = fmaf(m.y, f1.x, a1.x); a1.y = fmaf(m.y, f1.y, a1.y);
        a2.x = fmaf(m.z, f2.x, a2.x); a2.y = fmaf(m.z, f2.y, a2.y);
    }

    float i0 = g_dis[0 * N_NODES + v]; i0 *= i0;
    float i1 = g_dis[1 * N_NODES + v]; i1 *= i1;
    float i2 = g_dis[2 * N_NODES + v]; i2 *= i2;
    int sv = v * 64 + off;
    float2 s0 = uph2(h2a[sv]), s1 = uph2(h2b[sv]), s2 = uph2(h2c[sv]);
    int dcol = off * 2;                                   // 0..126 within D2
    float2 bb0 = *(const float2*)(b2 + 0 * D2 + dcol);
    float2 bb1 = *(const float2*)(b2 + 1 * D2 + dcol);
    float2 bb2 = *(const float2*)(b2 + 2 * D2 + dcol);

    a0.x = fmaxf(fmaf(i0, s0.x, a0.x) + bb0.x, 0.f);
    a0.y = fmaxf(fmaf(i0, s0.y, a0.y) + bb0.y, 0.f);
    a1.x = fmaxf(fmaf(i1, s1.x, a1.x) + bb1.x, 0.f);
    a1.y = fmaxf(fmaf(i1, s1.y, a1.y) + bb1.y, 0.f);
    a2.x = fmaxf(fmaf(i2, s2.x, a2.x) + bb2.x, 0.f);
    a2.y = fmaxf(fmaf(i2, s2.y, a2.y) + bb2.y, 0.f);

    int bt = v >> 13;
    int sq = (v >> 9) & 15;
    int vv = v & 511;
    int orow = bt * NNG + vv;
    long long base = ((long long)(orow * SEQ + sq)) * (NT * D2) + dcol;
    *(float2*)(out + base)          = a0;
    *(float2*)(out + base + D2)     = a1;
    *(float2*)(out + base + 2 * D2) = a2;
}

// ---------------- launch ----------------
extern "C" void kernel_launch(void* const* d_in, const int* in_sizes, int n_in,
                              void* d_out, int out_size) {
    const float* x  = (const float*)d_in[0];
    const float* ea = (const float*)d_in[1];
    const float* W1 = (const float*)d_in[2];
    const float* b1 = (const float*)d_in[3];
    const float* W2 = (const float*)d_in[4];
    const float* b2 = (const float*)d_in[5];
    const int*   ei = (const int*)d_in[6];
    float* out = (float*)d_out;

    __half *agg, *h1r, *h2;
    cudaGetSymbolAddress((void**)&agg, g_agg);
    cudaGetSymbolAddress((void**)&h1r, g_h1r);
    cudaGetSymbolAddress((void**)&h2,  g_h2);

    zero_kernel     <<<384, 256>>>();
    stats_kernel    <<<128, 128>>>(x);
    finstats_kernel <<<1, 128>>>();
    xnorm_kernel    <<<4096, 256>>>(x);
    hist_kernel     <<<E_EDGES / 256, 256>>>(ei, ea);
    scan_kernel     <<<1, 1024>>>();
    dis_kernel      <<<384, 256>>>();
    fill_kernel     <<<E_EDGES / 256, 256>>>(ei, ea);
    gather0_kernel  <<<N_NODES / 4, 256>>>();

    // h1r_t = relu(agg_t @ W1_t + b1_t)   [32768,128]@[128,256] -> fp16
    gemm_mma<<<dim3(D1 / 128, N_NODES / 128, NT), 256>>>(
        agg, (long long)N_NODES * F_IN, W1, (long long)F_IN * D1,
        h1r, (long long)N_NODES * D1, b1, D1,
        N_NODES, D1, F_IN, 1);

    // h2_t = h1r_t @ W2_t   [32768,256]@[256,128] -> fp16
    gemm_mma<<<dim3(D2 / 128, N_NODES / 128, NT), 256>>>(
        h1r, (long long)N_NODES * D1, W2, (long long)D1 * D2,
        h2, (long long)N_NODES * D2, (const float*)nullptr, 0,
        N_NODES, D2, D1, 0);

    gather2_kernel<<<N_NODES / 4, 256>>>(b2, out);
}